// round 14
// baseline (speedup 1.0000x reference)
#include <cuda_runtime.h>
#include <cuda_bf16.h>
#include <cstdint>

// Problem dims
#define B_   4
#define S_   4096
#define C_   1280
#define DC_  2048
#define H_   20
#define D_   64
#define LTXT 77
#define LIMG 4
#define LLBL 4
#define LTOT 85
#define KPAD 68
#define MTOT (B_ * S_)   // 16384

// ---------------------------------------------------------------------------
// Device scratch
// ---------------------------------------------------------------------------
__device__ float g_q[(size_t)MTOT * C_];                    // fp32 Q
__device__ __nv_bfloat16 g_ahi[(size_t)MTOT * C_];          // activation hi
__device__ __nv_bfloat16 g_alo[(size_t)MTOT * C_];          // activation lo
__device__ __nv_bfloat16 g_wqhi[(size_t)C_ * C_];           // Wq^T hi [N,K]
__device__ __nv_bfloat16 g_wqlo[(size_t)C_ * C_];           // Wq^T lo
__device__ __nv_bfloat16 g_wohi[(size_t)C_ * C_];           // Wo^T hi
__device__ float g_k[(size_t)B_ * LTOT * C_];
__device__ float g_v[(size_t)B_ * LTOT * C_];

// ---------------------------------------------------------------------------
// PTX helpers (stable ISA)
// ---------------------------------------------------------------------------
__device__ __forceinline__ uint32_t smem_u32(const void* p) {
    uint32_t a;
    asm("{ .reg .u64 t; cvta.to.shared.u64 t, %1; cvt.u32.u64 %0, t; }"
        : "=r"(a) : "l"(p));
    return a;
}
__device__ __forceinline__ void cp_async16(uint32_t dst, const void* src) {
    asm volatile("cp.async.cg.shared.global [%0], [%1], 16;" :: "r"(dst), "l"(src));
}
__device__ __forceinline__ void cp_commit() {
    asm volatile("cp.async.commit_group;");
}
__device__ __forceinline__ void cp_wait1() {
    asm volatile("cp.async.wait_group 1;");
}
__device__ __forceinline__ void ldsm_x4(uint32_t* r, uint32_t addr) {
    asm volatile("ldmatrix.sync.aligned.m8n8.x4.shared.b16 {%0,%1,%2,%3}, [%4];"
                 : "=r"(r[0]), "=r"(r[1]), "=r"(r[2]), "=r"(r[3]) : "r"(addr));
}
__device__ __forceinline__ void mma_bf16(float* c, const uint32_t* a,
                                         const uint32_t* b) {
    asm volatile(
        "mma.sync.aligned.m16n8k16.row.col.f32.bf16.bf16.f32 "
        "{%0,%1,%2,%3}, {%4,%5,%6,%7}, {%8,%9}, {%0,%1,%2,%3};"
        : "+f"(c[0]), "+f"(c[1]), "+f"(c[2]), "+f"(c[3])
        : "r"(a[0]), "r"(a[1]), "r"(a[2]), "r"(a[3]), "r"(b[0]), "r"(b[1]));
}

// ---------------------------------------------------------------------------
// Conversion kernels
// ---------------------------------------------------------------------------
__global__ void conv_split(const float* __restrict__ src,
                           __nv_bfloat16* __restrict__ hi,
                           __nv_bfloat16* __restrict__ lo, long long n4) {
    long long i = (long long)blockIdx.x * blockDim.x + threadIdx.x;
    if (i >= n4) return;
    float4 v = ((const float4*)src)[i];
    __nv_bfloat16 h[4], l[4];
    float f[4] = {v.x, v.y, v.z, v.w};
#pragma unroll
    for (int j = 0; j < 4; j++) {
        h[j] = __float2bfloat16(f[j]);
        l[j] = __float2bfloat16(f[j] - __bfloat162float(h[j]));
    }
    ((uint2*)hi)[i] = *(uint2*)h;
    ((uint2*)lo)[i] = *(uint2*)l;
}

// W (K x N fp32, row-major) -> Wt hi (and optional lo) (N x K bf16)
__global__ void conv_w_t(const float* __restrict__ W,
                         __nv_bfloat16* __restrict__ Thi,
                         __nv_bfloat16* __restrict__ Tlo) {
    __shared__ float t[32][33];
    const int n0 = blockIdx.x * 32, k0 = blockIdx.y * 32;
    const int tx = threadIdx.x, ty = threadIdx.y;  // 32 x 8
#pragma unroll
    for (int i = 0; i < 4; i++) {
        const int kk = ty + 8 * i;
        t[kk][tx] = W[(long long)(k0 + kk) * C_ + n0 + tx];
    }
    __syncthreads();
#pragma unroll
    for (int i = 0; i < 4; i++) {
        const int nn = ty + 8 * i;
        const float v = t[tx][nn];
        const __nv_bfloat16 h = __float2bfloat16(v);
        const long long o = (long long)(n0 + nn) * C_ + k0 + tx;
        Thi[o] = h;
        if (Tlo) Tlo[o] = __float2bfloat16(v - __bfloat162float(h));
    }
}

// ---------------------------------------------------------------------------
// bf16 split-precision GEMM via mma.sync, templated on #B-tiles.
// NB=2: D = AhiBhi + AhiBlo + AloBhi   (Q projection, full 3-product)
// NB=1: D = AhiBhi + AloBhi            (O projection, 2-product)
// CTA 128x256, 8 warps, warp tile 64x64, BK=32, 3-stage cp.async pipe.
// ---------------------------------------------------------------------------
#define GK     C_            // 1280
#define NIT    (GK / 32)     // 40
#define TILEA  (128 * 80)    // 10240 B
#define TILEBB (256 * 80)    // 20480 B
#define NSTAGE 3

template <int NB>
__device__ __forceinline__ void issue_stage(
    uint32_t sbase, const __nv_bfloat16* Ahi, const __nv_bfloat16* Alo,
    const __nv_bfloat16* Bhi, const __nv_bfloat16* Blo,
    int bm, int bn, int k0, int tid)
{
#pragma unroll
    for (int t = 0; t < 2; t++) {
        const __nv_bfloat16* s0 = (t == 0 ? Ahi : Alo) + (long long)bm * GK + k0;
#pragma unroll
        for (int i = 0; i < 2; i++) {
            const int c = tid + 256 * i;
            const int row = c >> 2, ch = c & 3;
            cp_async16(sbase + t * TILEA + row * 80 + ch * 16,
                       s0 + (long long)row * GK + ch * 8);
        }
    }
#pragma unroll
    for (int t = 0; t < NB; t++) {
        const __nv_bfloat16* s0 = (t == 0 ? Bhi : Blo) + (long long)bn * GK + k0;
#pragma unroll
        for (int i = 0; i < 4; i++) {
            const int c = tid + 256 * i;
            const int row = c >> 2, ch = c & 3;
            cp_async16(sbase + 2 * TILEA + t * TILEBB + row * 80 + ch * 16,
                       s0 + (long long)row * GK + ch * 8);
        }
    }
    cp_commit();
}

template <int NB>
__global__ __launch_bounds__(256, 1)
void gemm_mma(const __nv_bfloat16* __restrict__ Ahi,
              const __nv_bfloat16* __restrict__ Alo,
              const __nv_bfloat16* __restrict__ Bhi,
              const __nv_bfloat16* __restrict__ Blo,
              float* __restrict__ Cout,
              const float* __restrict__ bias,
              const float* __restrict__ resid)
{
    constexpr int STAGEB = 2 * TILEA + NB * TILEBB;
    extern __shared__ char smem[];
    const int tid  = threadIdx.x;
    const int warp = tid >> 5;
    const int lane = tid & 31;
    const int bm   = blockIdx.y * 128;
    const int bn   = blockIdx.x * 256;
    const uint32_t sb = smem_u32(smem);

    const int wm = (warp >> 2) * 64;   // 0 or 64
    const int wn = (warp & 3) * 64;    // 0,64,128,192

    float acc[4][8][4];
#pragma unroll
    for (int i = 0; i < 4; i++)
#pragma unroll
        for (int j = 0; j < 8; j++)
#pragma unroll
            for (int e = 0; e < 4; e++) acc[i][j][e] = 0.f;

    const int lmat = lane >> 3;
    const int lrow = lane & 7;
    const int aRow  = (lmat & 1) * 8 + lrow;
    const int aKoff = (lmat >> 1) * 8;
    const int bRow  = (lmat >> 1) * 8 + lrow;
    const int bKoff = (lmat & 1) * 8;

    issue_stage<NB>(sb + 0 * STAGEB, Ahi, Alo, Bhi, Blo, bm, bn, 0, tid);
    issue_stage<NB>(sb + 1 * STAGEB, Ahi, Alo, Bhi, Blo, bm, bn, 32, tid);

    int stage = 0;
    for (int it = 0; it < NIT; it++) {
        cp_wait1();
        __syncthreads();
        if (it + 2 < NIT) {
            int ns = stage + 2; if (ns >= NSTAGE) ns -= NSTAGE;
            issue_stage<NB>(sb + ns * STAGEB, Ahi, Alo, Bhi, Blo,
                            bm, bn, (it + 2) * 32, tid);
        } else {
            cp_commit();
        }

        const uint32_t st  = sb + stage * STAGEB;
        const uint32_t sAh = st, sAl = st + TILEA;
        const uint32_t sBh = st + 2 * TILEA;
        const uint32_t sBl = st + 2 * TILEA + TILEBB;

#pragma unroll
        for (int ks = 0; ks < 2; ks++) {
            uint32_t ah[4][4], al[4][4], bh[4][4], bl[4][4];
#pragma unroll
            for (int i = 0; i < 4; i++) {
                const uint32_t off =
                    (uint32_t)(wm + i * 16 + aRow) * 80 +
                    (uint32_t)(ks * 16 + aKoff) * 2;
                ldsm_x4(ah[i], sAh + off);
                ldsm_x4(al[i], sAl + off);
            }
#pragma unroll
            for (int jp = 0; jp < 4; jp++) {
                const uint32_t off =
                    (uint32_t)(wn + jp * 16 + bRow) * 80 +
                    (uint32_t)(ks * 16 + bKoff) * 2;
                ldsm_x4(bh[jp], sBh + off);
                if (NB == 2) ldsm_x4(bl[jp], sBl + off);
            }
            // hh product
#pragma unroll
            for (int i = 0; i < 4; i++)
#pragma unroll
                for (int jp = 0; jp < 4; jp++) {
                    mma_bf16(acc[i][2 * jp],     ah[i], &bh[jp][0]);
                    mma_bf16(acc[i][2 * jp + 1], ah[i], &bh[jp][2]);
                }
            // hl product (Q only)
            if (NB == 2) {
#pragma unroll
                for (int i = 0; i < 4; i++)
#pragma unroll
                    for (int jp = 0; jp < 4; jp++) {
                        mma_bf16(acc[i][2 * jp],     ah[i], &bl[jp][0]);
                        mma_bf16(acc[i][2 * jp + 1], ah[i], &bl[jp][2]);
                    }
            }
            // lh product
#pragma unroll
            for (int i = 0; i < 4; i++)
#pragma unroll
                for (int jp = 0; jp < 4; jp++) {
                    mma_bf16(acc[i][2 * jp],     al[i], &bh[jp][0]);
                    mma_bf16(acc[i][2 * jp + 1], al[i], &bh[jp][2]);
                }
        }
        if (++stage == NSTAGE) stage = 0;
    }

    // epilogue: acc -> gmem fp32 (+bias)(+resid)
#pragma unroll
    for (int i = 0; i < 4; i++) {
#pragma unroll
        for (int j = 0; j < 8; j++) {
            const int col = bn + wn + j * 8 + (lane & 3) * 2;
#pragma unroll
            for (int half = 0; half < 2; half++) {
                const long long row = bm + wm + i * 16 + (lane >> 2) + half * 8;
                float2 o;
                o.x = acc[i][j][half * 2 + 0];
                o.y = acc[i][j][half * 2 + 1];
                if (bias) { o.x += bias[col]; o.y += bias[col + 1]; }
                if (resid) {
                    const float2 rv = *(const float2*)(resid + row * C_ + col);
                    o.x += rv.x; o.y += rv.y;
                }
                *(float2*)(Cout + row * C_ + col) = o;
            }
        }
    }
}

// ---------------------------------------------------------------------------
// Split-K thin GEMM for KV projections (atomicAdd into zeroed output).
// ---------------------------------------------------------------------------
#define KSPLIT 8
#define KCHUNK (DC_ / KSPLIT)

__global__ __launch_bounds__(256)
void sgemm32s(const float* __restrict__ Abase,
              const float* __restrict__ Bw,
              float* __restrict__ Cbase,
              int M, long long strideA, long long strideC) {
    __shared__ float As[32][33];
    __shared__ float Bs[32][64];

    const float* A = Abase + (long long)blockIdx.z * strideA;
    float*       Cc = Cbase + (long long)blockIdx.z * strideC;

    const int rt = blockIdx.y / KSPLIT;
    const int ks = blockIdx.y % KSPLIT;
    const int bm = rt * 32;
    const int bn = blockIdx.x * 64;
    const int kc0 = ks * KCHUNK;

    const int tid = threadIdx.x;
    const int tx = tid & 15, ty = tid >> 4;
    const int aRow = tid >> 3, aCol = (tid & 7) << 2;
    const int bRow = tid >> 4, bCol = (tid & 15) << 2;

    float acc[2][4];
#pragma unroll
    for (int i = 0; i < 2; i++)
#pragma unroll
        for (int j = 0; j < 4; j++) acc[i][j] = 0.f;

    for (int k0 = kc0; k0 < kc0 + KCHUNK; k0 += 32) {
        float4 av = make_float4(0.f, 0.f, 0.f, 0.f);
        if (bm + aRow < M)
            av = *(const float4*)(A + (long long)(bm + aRow) * DC_ + k0 + aCol);
        As[aCol + 0][aRow] = av.x;
        As[aCol + 1][aRow] = av.y;
        As[aCol + 2][aRow] = av.z;
        As[aCol + 3][aRow] = av.w;
#pragma unroll
        for (int p = 0; p < 2; p++) {
            const int r = bRow + p * 16;
            *(float4*)&Bs[r][bCol] =
                *(const float4*)(Bw + (long long)(k0 + r) * C_ + bn + bCol);
        }
        __syncthreads();
#pragma unroll
        for (int kk = 0; kk < 32; kk++) {
            const float a0 = As[kk][ty * 2];
            const float a1 = As[kk][ty * 2 + 1];
            const float4 b = *(const float4*)&Bs[kk][tx * 4];
            acc[0][0] = fmaf(a0, b.x, acc[0][0]);
            acc[0][1] = fmaf(a0, b.y, acc[0][1]);
            acc[0][2] = fmaf(a0, b.z, acc[0][2]);
            acc[0][3] = fmaf(a0, b.w, acc[0][3]);
            acc[1][0] = fmaf(a1, b.x, acc[1][0]);
            acc[1][1] = fmaf(a1, b.y, acc[1][1]);
            acc[1][2] = fmaf(a1, b.z, acc[1][2]);
            acc[1][3] = fmaf(a1, b.w, acc[1][3]);
        }
        __syncthreads();
    }

#pragma unroll
    for (int i = 0; i < 2; i++) {
        const int r = bm + ty * 2 + i;
        if (r < M) {
            float* cp = Cc + (long long)r * C_ + bn + tx * 4;
#pragma unroll
            for (int j = 0; j < 4; j++) atomicAdd(cp + j, acc[i][j]);
        }
    }
}

// ---------------------------------------------------------------------------
// Fused 3-branch cross-attention, v3: 4 queries per warp.
// Per-batch launch: batch index passed as parameter, grid (H_, 16).
// Math identical to round 12/13.
// ---------------------------------------------------------------------------
#define ATTN_SMEM ((2 * LTOT * KPAD + 8 * 4 * 88) * 4)

__global__ __launch_bounds__(256, 2)
void attn_kernel(const float* __restrict__ q,
                 const float* __restrict__ kall,
                 const float* __restrict__ vall,
                 __nv_bfloat16* __restrict__ ohi,
                 __nv_bfloat16* __restrict__ olo,
                 int b) {
    extern __shared__ float sm[];
    float* Ksh = sm;
    float* Vsh = sm + LTOT * KPAD;
    float* Pall = sm + 2 * LTOT * KPAD;   // [8][4][88]

    const int h = blockIdx.x;
    const int tid = threadIdx.x, lane = tid & 31, warp = tid >> 5;

    for (int i = tid; i < LTOT * D_; i += 256) {
        const int l = i >> 6, d = i & 63;
        const long long g = ((long long)b * LTOT + l) * C_ + h * D_ + d;
        Ksh[l * KPAD + d] = kall[g];
        Vsh[l * KPAD + d] = vall[g];
    }
    __syncthreads();

    const int sPer = S_ / gridDim.y;
    const int s0 = blockIdx.y * sPer;
    const float scale = 0.125f;

    const int k2idx = (lane < 13) ? (64 + lane) : ((lane >= 24) ? (53 + lane) : 0);
    const float* K0 = Ksh + lane * KPAD;
    const float* K1 = Ksh + (lane + 32) * KPAD;
    const float* K2 = Ksh + k2idx * KPAD;
    float* P0 = Pall + (warp * 4 + 0) * 88;
    float* P1 = Pall + (warp * 4 + 1) * 88;
    float* P2 = Pall + (warp * 4 + 2) * 88;
    float* P3 = Pall + (warp * 4 + 3) * 88;
    float* const Pq[4] = {P0, P1, P2, P3};

    const bool isTxt2 = (lane < 13);

    for (int s = s0 + warp * 4; s < s0 + sPer; s += 32) {
        const float* qp = q + ((long long)b * S_ + s) * C_ + h * D_;

        float sc0[4], sc1[4], sc2[4];
#pragma unroll
        for (int qq = 0; qq < 4; qq++) { sc0[qq] = 0.f; sc1[qq] = 0.f; sc2[qq] = 0.f; }

#pragma unroll 4
        for (int i = 0; i < 16; i++) {
            const int d = i * 4;
            const float4 k0 = *(const float4*)(K0 + d);
            const float4 k1 = *(const float4*)(K1 + d);
            const float4 k2 = *(const float4*)(K2 + d);
#pragma unroll
            for (int qq = 0; qq < 4; qq++) {
                const float4 qv = *(const float4*)(qp + (long long)qq * C_ + d);
                sc0[qq] = fmaf(qv.x, k0.x, sc0[qq]);
                sc0[qq] = fmaf(qv.y, k0.y, sc0[qq]);
                sc0[qq] = fmaf(qv.z, k0.z, sc0[qq]);
                sc0[qq] = fmaf(qv.w, k0.w, sc0[qq]);
                sc1[qq] = fmaf(qv.x, k1.x, sc1[qq]);
                sc1[qq] = fmaf(qv.y, k1.y, sc1[qq]);
                sc1[qq] = fmaf(qv.z, k1.z, sc1[qq]);
                sc1[qq] = fmaf(qv.w, k1.w, sc1[qq]);
                sc2[qq] = fmaf(qv.x, k2.x, sc2[qq]);
                sc2[qq] = fmaf(qv.y, k2.y, sc2[qq]);
                sc2[qq] = fmaf(qv.z, k2.z, sc2[qq]);
                sc2[qq] = fmaf(qv.w, k2.w, sc2[qq]);
            }
        }
#pragma unroll
        for (int qq = 0; qq < 4; qq++) {
            sc0[qq] *= scale; sc1[qq] *= scale; sc2[qq] *= scale;
        }

        float m[4], tsum[4], e0[4], e1[4], e2[4], inv[4];
#pragma unroll
        for (int qq = 0; qq < 4; qq++) {
            m[qq] = fmaxf(sc0[qq], sc1[qq]);
            if (isTxt2) m[qq] = fmaxf(m[qq], sc2[qq]);
        }
#pragma unroll
        for (int off = 16; off > 0; off >>= 1) {
#pragma unroll
            for (int qq = 0; qq < 4; qq++)
                m[qq] = fmaxf(m[qq], __shfl_xor_sync(0xffffffffu, m[qq], off));
        }
#pragma unroll
        for (int qq = 0; qq < 4; qq++) {
            e0[qq] = __expf(sc0[qq] - m[qq]);
            e1[qq] = __expf(sc1[qq] - m[qq]);
            e2[qq] = isTxt2 ? __expf(sc2[qq] - m[qq]) : 0.f;
            tsum[qq] = e0[qq] + e1[qq] + e2[qq];
        }
#pragma unroll
        for (int off = 16; off > 0; off >>= 1) {
#pragma unroll
            for (int qq = 0; qq < 4; qq++)
                tsum[qq] += __shfl_xor_sync(0xffffffffu, tsum[qq], off);
        }
#pragma unroll
        for (int qq = 0; qq < 4; qq++) inv[qq] = 1.f / tsum[qq];

        float pg[4];
#pragma unroll
        for (int qq = 0; qq < 4; qq++) {
            float g = sc2[qq];
            g = fmaxf(g, __shfl_xor_sync(0xffffffffu, g, 1));
            g = fmaxf(g, __shfl_xor_sync(0xffffffffu, g, 2));
            const float eg = __expf(sc2[qq] - g);
            float gs = eg;
            gs += __shfl_xor_sync(0xffffffffu, gs, 1);
            gs += __shfl_xor_sync(0xffffffffu, gs, 2);
            pg[qq] = eg / gs;
        }

#pragma unroll
        for (int qq = 0; qq < 4; qq++) {
            Pq[qq][lane]      = e0[qq] * inv[qq];
            Pq[qq][lane + 32] = e1[qq] * inv[qq];
            if (isTxt2)     Pq[qq][lane + 64] = e2[qq] * inv[qq];
            if (lane >= 24) Pq[qq][lane + 53] = pg[qq];
        }
        __syncwarp();

        float o0[4], o1[4];
#pragma unroll
        for (int qq = 0; qq < 4; qq++) { o0[qq] = 0.f; o1[qq] = 0.f; }
#pragma unroll 5
        for (int k = 0; k < LTOT; k++) {
            const float v0 = Vsh[k * KPAD + lane];
            const float v1 = Vsh[k * KPAD + lane + 32];
#pragma unroll
            for (int qq = 0; qq < 4; qq++) {
                const float p = Pq[qq][k];
                o0[qq] = fmaf(p, v0, o0[qq]);
                o1[qq] = fmaf(p, v1, o1[qq]);
            }
        }

#pragma unroll
        for (int qq = 0; qq < 4; qq++) {
            const long long base = ((long long)b * S_ + s + qq) * C_ + h * D_;
            const __nv_bfloat16 h0 = __float2bfloat16(o0[qq]);
            const __nv_bfloat16 h1 = __float2bfloat16(o1[qq]);
            ohi[base + lane]      = h0;
            ohi[base + lane + 32] = h1;
            olo[base + lane]      = __float2bfloat16(o0[qq] - __bfloat162float(h0));
            olo[base + lane + 32] = __float2bfloat16(o1[qq] - __bfloat162float(h1));
        }
        __syncwarp();
    }
}

// ---------------------------------------------------------------------------
// Launch — per-batch software pipeline:
//   main: conv -> QG(b=0..3) -> OG(b=0..3, each gated on attn(b))
//   s2:   memsets + KV + Wo-conv, then attn(b) gated on QG(b)
// Attention (FMA-bound) hides under the GEMM stream (tensor-bound).
// ---------------------------------------------------------------------------
extern "C" void kernel_launch(void* const* d_in, const int* in_sizes, int n_in,
                              void* d_out, int out_size) {
    const float* hidden = (const float*)d_in[0];
    const float* enc    = (const float*)d_in[1];
    const float* Wq     = (const float*)d_in[2];
    const float* Wk     = (const float*)d_in[3];
    const float* Wv     = (const float*)d_in[4];
    const float* Wk_ip  = (const float*)d_in[5];
    const float* Wv_ip  = (const float*)d_in[6];
    const float* Wk_lbl = (const float*)d_in[7];
    const float* Wv_lbl = (const float*)d_in[8];
    const float* Wo     = (const float*)d_in[9];
    const float* bo     = (const float*)d_in[10];
    float* out = (float*)d_out;

    float *qb, *kb, *vb;
    __nv_bfloat16 *ahi, *alo, *wqhi, *wqlo, *wohi;
    cudaGetSymbolAddress((void**)&qb, g_q);
    cudaGetSymbolAddress((void**)&kb, g_k);
    cudaGetSymbolAddress((void**)&vb, g_v);
    cudaGetSymbolAddress((void**)&ahi, g_ahi);
    cudaGetSymbolAddress((void**)&alo, g_alo);
    cudaGetSymbolAddress((void**)&wqhi, g_wqhi);
    cudaGetSymbolAddress((void**)&wqlo, g_wqlo);
    cudaGetSymbolAddress((void**)&wohi, g_wohi);

    // One-time host-side stream/event objects (no device memory involved).
    static cudaStream_t s2 = nullptr;
    static cudaEvent_t evFork = nullptr;
    static cudaEvent_t evQG[B_] = {}, evA[B_] = {};
    if (s2 == nullptr) {
        cudaStreamCreateWithFlags(&s2, cudaStreamNonBlocking);
        cudaEventCreateWithFlags(&evFork, cudaEventDisableTiming);
        for (int b = 0; b < B_; b++) {
            cudaEventCreateWithFlags(&evQG[b], cudaEventDisableTiming);
            cudaEventCreateWithFlags(&evA[b], cudaEventDisableTiming);
        }
    }

    const int SMEM_Q = NSTAGE * (2 * TILEA + 2 * TILEBB);   // 184320
    const int SMEM_O = NSTAGE * (2 * TILEA + 1 * TILEBB);   // 122880
    cudaFuncSetAttribute(gemm_mma<2>,
                         cudaFuncAttributeMaxDynamicSharedMemorySize, SMEM_Q);
    cudaFuncSetAttribute(gemm_mma<1>,
                         cudaFuncAttributeMaxDynamicSharedMemorySize, SMEM_O);
    cudaFuncSetAttribute(attn_kernel,
                         cudaFuncAttributeMaxDynamicSharedMemorySize, ATTN_SMEM);

    const long long chunkElems = (long long)S_ * C_;   // rows per batch * C

    // ---- fork ----
    cudaEventRecord(evFork, 0);
    cudaStreamWaitEvent(s2, evFork, 0);

    // ---- s2 branch: memsets + KV projections + Wo conversion ----
    {
        cudaMemsetAsync(kb, 0, (size_t)B_ * LTOT * C_ * sizeof(float), s2);
        cudaMemsetAsync(vb, 0, (size_t)B_ * LTOT * C_ * sizeof(float), s2);
        const long long sA = (long long)LTOT * DC_;
        const long long sC = (long long)LTOT * C_;
        dim3 blk(256);
        dim3 gT(C_ / 64, 3 * KSPLIT, B_);
        dim3 gS(C_ / 64, 1 * KSPLIT, B_);
        sgemm32s<<<gT, blk, 0, s2>>>(enc, Wk, kb, LTXT, sA, sC);
        sgemm32s<<<gT, blk, 0, s2>>>(enc, Wv, vb, LTXT, sA, sC);
        sgemm32s<<<gS, blk, 0, s2>>>(enc + (long long)LTXT * DC_, Wk_ip,
                                     kb + (long long)LTXT * C_, LIMG, sA, sC);
        sgemm32s<<<gS, blk, 0, s2>>>(enc + (long long)LTXT * DC_, Wv_ip,
                                     vb + (long long)LTXT * C_, LIMG, sA, sC);
        sgemm32s<<<gS, blk, 0, s2>>>(enc + (long long)(LTXT + LIMG) * DC_, Wk_lbl,
                                     kb + (long long)(LTXT + LIMG) * C_, LLBL, sA, sC);
        sgemm32s<<<gS, blk, 0, s2>>>(enc + (long long)(LTXT + LIMG) * DC_, Wv_lbl,
                                     vb + (long long)(LTXT + LIMG) * C_, LLBL, sA, sC);
        dim3 gw(C_ / 32, C_ / 32), bw(32, 8);
        conv_w_t<<<gw, bw, 0, s2>>>(Wo, wohi, nullptr);
    }

    // ---- main branch: conversions for Q ----
    {
        const long long n4 = (long long)MTOT * C_ / 4;
        conv_split<<<(unsigned)((n4 + 255) / 256), 256>>>(hidden, ahi, alo, n4);
        dim3 gw(C_ / 32, C_ / 32), bw(32, 8);
        conv_w_t<<<gw, bw>>>(Wq, wqhi, wqlo);
    }

    // ---- Q projection, per-batch chunks, each followed by an event ----
    for (int b = 0; b < B_; b++) {
        const long long off = (long long)b * chunkElems;
        gemm_mma<2><<<dim3(C_ / 256, S_ / 128), 256, SMEM_Q>>>(
            ahi + off, alo + off, wqhi, wqlo, qb + off, nullptr, nullptr);
        cudaEventRecord(evQG[b], 0);
    }

    // ---- s2: attention per batch, gated on the matching Q chunk ----
    for (int b = 0; b < B_; b++) {
        cudaStreamWaitEvent(s2, evQG[b], 0);
        attn_kernel<<<dim3(H_, 16), 256, ATTN_SMEM, s2>>>(qb, kb, vb, ahi, alo, b);
        cudaEventRecord(evA[b], s2);
    }

    // ---- main: O projection per batch, gated on matching attention chunk ----
    for (int b = 0; b < B_; b++) {
        cudaStreamWaitEvent(0, evA[b], 0);
        const long long off = (long long)b * chunkElems;
        gemm_mma<1><<<dim3(C_ / 256, S_ / 128), 256, SMEM_O>>>(
            ahi + off, alo + off, wohi, nullptr, out + off, bo, hidden + off);
    }
}

// round 15
// speedup vs baseline: 1.0798x; 1.0798x over previous
#include <cuda_runtime.h>
#include <cuda_bf16.h>
#include <cstdint>

// Problem dims
#define B_   4
#define S_   4096
#define C_   1280
#define DC_  2048
#define H_   20
#define D_   64
#define LTXT 77
#define LIMG 4
#define LLBL 4
#define LTOT 85
#define KPAD 68
#define MTOT (B_ * S_)   // 16384

// ---------------------------------------------------------------------------
// Device scratch
// ---------------------------------------------------------------------------
__device__ float g_q[(size_t)MTOT * C_];                    // fp32 Q
__device__ __nv_bfloat16 g_ahi[(size_t)MTOT * C_];          // activation hi
__device__ __nv_bfloat16 g_alo[(size_t)MTOT * C_];          // activation lo
__device__ __nv_bfloat16 g_wqhi[(size_t)C_ * C_];           // Wq^T hi [N,K]
__device__ __nv_bfloat16 g_wqlo[(size_t)C_ * C_];           // Wq^T lo
__device__ __nv_bfloat16 g_wohi[(size_t)C_ * C_];           // Wo^T hi
__device__ float g_k[(size_t)B_ * LTOT * C_];
__device__ float g_v[(size_t)B_ * LTOT * C_];

// ---------------------------------------------------------------------------
// PTX helpers (stable ISA)
// ---------------------------------------------------------------------------
__device__ __forceinline__ uint32_t smem_u32(const void* p) {
    uint32_t a;
    asm("{ .reg .u64 t; cvta.to.shared.u64 t, %1; cvt.u32.u64 %0, t; }"
        : "=r"(a) : "l"(p));
    return a;
}
__device__ __forceinline__ void cp_async16(uint32_t dst, const void* src) {
    asm volatile("cp.async.cg.shared.global [%0], [%1], 16;" :: "r"(dst), "l"(src));
}
__device__ __forceinline__ void cp_commit() {
    asm volatile("cp.async.commit_group;");
}
__device__ __forceinline__ void cp_wait1() {
    asm volatile("cp.async.wait_group 1;");
}
__device__ __forceinline__ void ldsm_x4(uint32_t* r, uint32_t addr) {
    asm volatile("ldmatrix.sync.aligned.m8n8.x4.shared.b16 {%0,%1,%2,%3}, [%4];"
                 : "=r"(r[0]), "=r"(r[1]), "=r"(r[2]), "=r"(r[3]) : "r"(addr));
}
__device__ __forceinline__ void mma_bf16(float* c, const uint32_t* a,
                                         const uint32_t* b) {
    asm volatile(
        "mma.sync.aligned.m16n8k16.row.col.f32.bf16.bf16.f32 "
        "{%0,%1,%2,%3}, {%4,%5,%6,%7}, {%8,%9}, {%0,%1,%2,%3};"
        : "+f"(c[0]), "+f"(c[1]), "+f"(c[2]), "+f"(c[3])
        : "r"(a[0]), "r"(a[1]), "r"(a[2]), "r"(a[3]), "r"(b[0]), "r"(b[1]));
}

// ---------------------------------------------------------------------------
// Conversion kernels
// ---------------------------------------------------------------------------
__global__ void conv_split(const float* __restrict__ src,
                           __nv_bfloat16* __restrict__ hi,
                           __nv_bfloat16* __restrict__ lo, long long n4) {
    long long i = (long long)blockIdx.x * blockDim.x + threadIdx.x;
    if (i >= n4) return;
    float4 v = ((const float4*)src)[i];
    __nv_bfloat16 h[4], l[4];
    float f[4] = {v.x, v.y, v.z, v.w};
#pragma unroll
    for (int j = 0; j < 4; j++) {
        h[j] = __float2bfloat16(f[j]);
        l[j] = __float2bfloat16(f[j] - __bfloat162float(h[j]));
    }
    ((uint2*)hi)[i] = *(uint2*)h;
    ((uint2*)lo)[i] = *(uint2*)l;
}

// W (K x N fp32, row-major) -> Wt hi (and optional lo) (N x K bf16)
__global__ void conv_w_t(const float* __restrict__ W,
                         __nv_bfloat16* __restrict__ Thi,
                         __nv_bfloat16* __restrict__ Tlo) {
    __shared__ float t[32][33];
    const int n0 = blockIdx.x * 32, k0 = blockIdx.y * 32;
    const int tx = threadIdx.x, ty = threadIdx.y;  // 32 x 8
#pragma unroll
    for (int i = 0; i < 4; i++) {
        const int kk = ty + 8 * i;
        t[kk][tx] = W[(long long)(k0 + kk) * C_ + n0 + tx];
    }
    __syncthreads();
#pragma unroll
    for (int i = 0; i < 4; i++) {
        const int nn = ty + 8 * i;
        const float v = t[tx][nn];
        const __nv_bfloat16 h = __float2bfloat16(v);
        const long long o = (long long)(n0 + nn) * C_ + k0 + tx;
        Thi[o] = h;
        if (Tlo) Tlo[o] = __float2bfloat16(v - __bfloat162float(h));
    }
}

// ---------------------------------------------------------------------------
// bf16 split-precision GEMM via mma.sync, templated on #B-tiles.
// NB=2: D = AhiBhi + AhiBlo + AloBhi   (Q projection, full 3-product)
// NB=1: D = AhiBhi + AloBhi            (O projection, 2-product)
// CTA 128x256, 8 warps, warp tile 64x64, BK=32, 3-stage cp.async pipe.
// ---------------------------------------------------------------------------
#define GK     C_            // 1280
#define NIT    (GK / 32)     // 40
#define TILEA  (128 * 80)    // 10240 B
#define TILEBB (256 * 80)    // 20480 B
#define NSTAGE 3

template <int NB>
__device__ __forceinline__ void issue_stage(
    uint32_t sbase, const __nv_bfloat16* Ahi, const __nv_bfloat16* Alo,
    const __nv_bfloat16* Bhi, const __nv_bfloat16* Blo,
    int bm, int bn, int k0, int tid)
{
#pragma unroll
    for (int t = 0; t < 2; t++) {
        const __nv_bfloat16* s0 = (t == 0 ? Ahi : Alo) + (long long)bm * GK + k0;
#pragma unroll
        for (int i = 0; i < 2; i++) {
            const int c = tid + 256 * i;
            const int row = c >> 2, ch = c & 3;
            cp_async16(sbase + t * TILEA + row * 80 + ch * 16,
                       s0 + (long long)row * GK + ch * 8);
        }
    }
#pragma unroll
    for (int t = 0; t < NB; t++) {
        const __nv_bfloat16* s0 = (t == 0 ? Bhi : Blo) + (long long)bn * GK + k0;
#pragma unroll
        for (int i = 0; i < 4; i++) {
            const int c = tid + 256 * i;
            const int row = c >> 2, ch = c & 3;
            cp_async16(sbase + 2 * TILEA + t * TILEBB + row * 80 + ch * 16,
                       s0 + (long long)row * GK + ch * 8);
        }
    }
    cp_commit();
}

template <int NB>
__global__ __launch_bounds__(256, 1)
void gemm_mma(const __nv_bfloat16* __restrict__ Ahi,
              const __nv_bfloat16* __restrict__ Alo,
              const __nv_bfloat16* __restrict__ Bhi,
              const __nv_bfloat16* __restrict__ Blo,
              float* __restrict__ Cout,
              const float* __restrict__ bias,
              const float* __restrict__ resid)
{
    constexpr int STAGEB = 2 * TILEA + NB * TILEBB;
    extern __shared__ char smem[];
    const int tid  = threadIdx.x;
    const int warp = tid >> 5;
    const int lane = tid & 31;
    const int bm   = blockIdx.y * 128;
    const int bn   = blockIdx.x * 256;
    const uint32_t sb = smem_u32(smem);

    const int wm = (warp >> 2) * 64;   // 0 or 64
    const int wn = (warp & 3) * 64;    // 0,64,128,192

    float acc[4][8][4];
#pragma unroll
    for (int i = 0; i < 4; i++)
#pragma unroll
        for (int j = 0; j < 8; j++)
#pragma unroll
            for (int e = 0; e < 4; e++) acc[i][j][e] = 0.f;

    const int lmat = lane >> 3;
    const int lrow = lane & 7;
    const int aRow  = (lmat & 1) * 8 + lrow;
    const int aKoff = (lmat >> 1) * 8;
    const int bRow  = (lmat >> 1) * 8 + lrow;
    const int bKoff = (lmat & 1) * 8;

    issue_stage<NB>(sb + 0 * STAGEB, Ahi, Alo, Bhi, Blo, bm, bn, 0, tid);
    issue_stage<NB>(sb + 1 * STAGEB, Ahi, Alo, Bhi, Blo, bm, bn, 32, tid);

    int stage = 0;
    for (int it = 0; it < NIT; it++) {
        cp_wait1();
        __syncthreads();
        if (it + 2 < NIT) {
            int ns = stage + 2; if (ns >= NSTAGE) ns -= NSTAGE;
            issue_stage<NB>(sb + ns * STAGEB, Ahi, Alo, Bhi, Blo,
                            bm, bn, (it + 2) * 32, tid);
        } else {
            cp_commit();
        }

        const uint32_t st  = sb + stage * STAGEB;
        const uint32_t sAh = st, sAl = st + TILEA;
        const uint32_t sBh = st + 2 * TILEA;
        const uint32_t sBl = st + 2 * TILEA + TILEBB;

#pragma unroll
        for (int ks = 0; ks < 2; ks++) {
            uint32_t ah[4][4], al[4][4], bh[4][4], bl[4][4];
#pragma unroll
            for (int i = 0; i < 4; i++) {
                const uint32_t off =
                    (uint32_t)(wm + i * 16 + aRow) * 80 +
                    (uint32_t)(ks * 16 + aKoff) * 2;
                ldsm_x4(ah[i], sAh + off);
                ldsm_x4(al[i], sAl + off);
            }
#pragma unroll
            for (int jp = 0; jp < 4; jp++) {
                const uint32_t off =
                    (uint32_t)(wn + jp * 16 + bRow) * 80 +
                    (uint32_t)(ks * 16 + bKoff) * 2;
                ldsm_x4(bh[jp], sBh + off);
                if (NB == 2) ldsm_x4(bl[jp], sBl + off);
            }
            // hh product
#pragma unroll
            for (int i = 0; i < 4; i++)
#pragma unroll
                for (int jp = 0; jp < 4; jp++) {
                    mma_bf16(acc[i][2 * jp],     ah[i], &bh[jp][0]);
                    mma_bf16(acc[i][2 * jp + 1], ah[i], &bh[jp][2]);
                }
            // hl product (Q only)
            if (NB == 2) {
#pragma unroll
                for (int i = 0; i < 4; i++)
#pragma unroll
                    for (int jp = 0; jp < 4; jp++) {
                        mma_bf16(acc[i][2 * jp],     ah[i], &bl[jp][0]);
                        mma_bf16(acc[i][2 * jp + 1], ah[i], &bl[jp][2]);
                    }
            }
            // lh product
#pragma unroll
            for (int i = 0; i < 4; i++)
#pragma unroll
                for (int jp = 0; jp < 4; jp++) {
                    mma_bf16(acc[i][2 * jp],     al[i], &bh[jp][0]);
                    mma_bf16(acc[i][2 * jp + 1], al[i], &bh[jp][2]);
                }
        }
        if (++stage == NSTAGE) stage = 0;
    }

    // epilogue: acc -> gmem fp32 (+bias)(+resid)
#pragma unroll
    for (int i = 0; i < 4; i++) {
#pragma unroll
        for (int j = 0; j < 8; j++) {
            const int col = bn + wn + j * 8 + (lane & 3) * 2;
#pragma unroll
            for (int half = 0; half < 2; half++) {
                const long long row = bm + wm + i * 16 + (lane >> 2) + half * 8;
                float2 o;
                o.x = acc[i][j][half * 2 + 0];
                o.y = acc[i][j][half * 2 + 1];
                if (bias) { o.x += bias[col]; o.y += bias[col + 1]; }
                if (resid) {
                    const float2 rv = *(const float2*)(resid + row * C_ + col);
                    o.x += rv.x; o.y += rv.y;
                }
                *(float2*)(Cout + row * C_ + col) = o;
            }
        }
    }
}

// ---------------------------------------------------------------------------
// Split-K thin GEMM for KV projections (atomicAdd into zeroed output).
// ---------------------------------------------------------------------------
#define KSPLIT 8
#define KCHUNK (DC_ / KSPLIT)

__global__ __launch_bounds__(256)
void sgemm32s(const float* __restrict__ Abase,
              const float* __restrict__ Bw,
              float* __restrict__ Cbase,
              int M, long long strideA, long long strideC) {
    __shared__ float As[32][33];
    __shared__ float Bs[32][64];

    const float* A = Abase + (long long)blockIdx.z * strideA;
    float*       Cc = Cbase + (long long)blockIdx.z * strideC;

    const int rt = blockIdx.y / KSPLIT;
    const int ks = blockIdx.y % KSPLIT;
    const int bm = rt * 32;
    const int bn = blockIdx.x * 64;
    const int kc0 = ks * KCHUNK;

    const int tid = threadIdx.x;
    const int tx = tid & 15, ty = tid >> 4;
    const int aRow = tid >> 3, aCol = (tid & 7) << 2;
    const int bRow = tid >> 4, bCol = (tid & 15) << 2;

    float acc[2][4];
#pragma unroll
    for (int i = 0; i < 2; i++)
#pragma unroll
        for (int j = 0; j < 4; j++) acc[i][j] = 0.f;

    for (int k0 = kc0; k0 < kc0 + KCHUNK; k0 += 32) {
        float4 av = make_float4(0.f, 0.f, 0.f, 0.f);
        if (bm + aRow < M)
            av = *(const float4*)(A + (long long)(bm + aRow) * DC_ + k0 + aCol);
        As[aCol + 0][aRow] = av.x;
        As[aCol + 1][aRow] = av.y;
        As[aCol + 2][aRow] = av.z;
        As[aCol + 3][aRow] = av.w;
#pragma unroll
        for (int p = 0; p < 2; p++) {
            const int r = bRow + p * 16;
            *(float4*)&Bs[r][bCol] =
                *(const float4*)(Bw + (long long)(k0 + r) * C_ + bn + bCol);
        }
        __syncthreads();
#pragma unroll
        for (int kk = 0; kk < 32; kk++) {
            const float a0 = As[kk][ty * 2];
            const float a1 = As[kk][ty * 2 + 1];
            const float4 b = *(const float4*)&Bs[kk][tx * 4];
            acc[0][0] = fmaf(a0, b.x, acc[0][0]);
            acc[0][1] = fmaf(a0, b.y, acc[0][1]);
            acc[0][2] = fmaf(a0, b.z, acc[0][2]);
            acc[0][3] = fmaf(a0, b.w, acc[0][3]);
            acc[1][0] = fmaf(a1, b.x, acc[1][0]);
            acc[1][1] = fmaf(a1, b.y, acc[1][1]);
            acc[1][2] = fmaf(a1, b.z, acc[1][2]);
            acc[1][3] = fmaf(a1, b.w, acc[1][3]);
        }
        __syncthreads();
    }

#pragma unroll
    for (int i = 0; i < 2; i++) {
        const int r = bm + ty * 2 + i;
        if (r < M) {
            float* cp = Cc + (long long)r * C_ + bn + tx * 4;
#pragma unroll
            for (int j = 0; j < 4; j++) atomicAdd(cp + j, acc[i][j]);
        }
    }
}

// ---------------------------------------------------------------------------
// Fused 3-branch cross-attention, v4: 8 queries per warp.
// K/V smem bytes amortized over 8 queries. Per-query math order identical
// to v3 (d-ascending FMA chains, same accumulators) -> numerics unchanged.
// ---------------------------------------------------------------------------
#define NQ 8
#define ATTN_SMEM ((2 * LTOT * KPAD + 8 * NQ * 88) * 4)

__global__ __launch_bounds__(256, 2)
void attn_kernel(const float* __restrict__ q,
                 const float* __restrict__ kall,
                 const float* __restrict__ vall,
                 __nv_bfloat16* __restrict__ ohi,
                 __nv_bfloat16* __restrict__ olo) {
    extern __shared__ float sm[];
    float* Ksh = sm;
    float* Vsh = sm + LTOT * KPAD;
    float* Pall = sm + 2 * LTOT * KPAD;   // [8 warps][NQ][88]

    const int bh = blockIdx.x;
    const int b = bh / H_, h = bh % H_;
    const int tid = threadIdx.x, lane = tid & 31, warp = tid >> 5;

    for (int i = tid; i < LTOT * D_; i += 256) {
        const int l = i >> 6, d = i & 63;
        const long long g = ((long long)b * LTOT + l) * C_ + h * D_ + d;
        Ksh[l * KPAD + d] = kall[g];
        Vsh[l * KPAD + d] = vall[g];
    }
    __syncthreads();

    const int sPer = S_ / gridDim.y;
    const int s0 = blockIdx.y * sPer;
    const float scale = 0.125f;

    const int k2idx = (lane < 13) ? (64 + lane) : ((lane >= 24) ? (53 + lane) : 0);
    const float* K0 = Ksh + lane * KPAD;
    const float* K1 = Ksh + (lane + 32) * KPAD;
    const float* K2 = Ksh + k2idx * KPAD;
    float* Pw = Pall + warp * NQ * 88;

    const bool isTxt2 = (lane < 13);

    for (int s = s0 + warp * NQ; s < s0 + sPer; s += 8 * NQ) {
        const float* qp = q + ((long long)b * S_ + s) * C_ + h * D_;

        float sc0[NQ], sc1[NQ], sc2[NQ];
#pragma unroll
        for (int qq = 0; qq < NQ; qq++) { sc0[qq] = 0.f; sc1[qq] = 0.f; sc2[qq] = 0.f; }

        // ---- scores: 16 steps of 4 dims; K rows shared across NQ queries ----
#pragma unroll 2
        for (int i = 0; i < 16; i++) {
            const int d = i * 4;
            const float4 k0 = *(const float4*)(K0 + d);
            const float4 k1 = *(const float4*)(K1 + d);
            const float4 k2 = *(const float4*)(K2 + d);
#pragma unroll
            for (int qq = 0; qq < NQ; qq++) {
                const float4 qv = *(const float4*)(qp + (long long)qq * C_ + d);
                sc0[qq] = fmaf(qv.x, k0.x, sc0[qq]);
                sc0[qq] = fmaf(qv.y, k0.y, sc0[qq]);
                sc0[qq] = fmaf(qv.z, k0.z, sc0[qq]);
                sc0[qq] = fmaf(qv.w, k0.w, sc0[qq]);
                sc1[qq] = fmaf(qv.x, k1.x, sc1[qq]);
                sc1[qq] = fmaf(qv.y, k1.y, sc1[qq]);
                sc1[qq] = fmaf(qv.z, k1.z, sc1[qq]);
                sc1[qq] = fmaf(qv.w, k1.w, sc1[qq]);
                sc2[qq] = fmaf(qv.x, k2.x, sc2[qq]);
                sc2[qq] = fmaf(qv.y, k2.y, sc2[qq]);
                sc2[qq] = fmaf(qv.z, k2.z, sc2[qq]);
                sc2[qq] = fmaf(qv.w, k2.w, sc2[qq]);
            }
        }
#pragma unroll
        for (int qq = 0; qq < NQ; qq++) {
            sc0[qq] *= scale; sc1[qq] *= scale; sc2[qq] *= scale;
        }

        // ---- text softmax (keys 0..76), per query ----
        float m[NQ], tsum[NQ], e0[NQ], e1[NQ], e2[NQ], inv[NQ];
#pragma unroll
        for (int qq = 0; qq < NQ; qq++) {
            m[qq] = fmaxf(sc0[qq], sc1[qq]);
            if (isTxt2) m[qq] = fmaxf(m[qq], sc2[qq]);
        }
#pragma unroll
        for (int off = 16; off > 0; off >>= 1) {
#pragma unroll
            for (int qq = 0; qq < NQ; qq++)
                m[qq] = fmaxf(m[qq], __shfl_xor_sync(0xffffffffu, m[qq], off));
        }
#pragma unroll
        for (int qq = 0; qq < NQ; qq++) {
            e0[qq] = __expf(sc0[qq] - m[qq]);
            e1[qq] = __expf(sc1[qq] - m[qq]);
            e2[qq] = isTxt2 ? __expf(sc2[qq] - m[qq]) : 0.f;
            tsum[qq] = e0[qq] + e1[qq] + e2[qq];
        }
#pragma unroll
        for (int off = 16; off > 0; off >>= 1) {
#pragma unroll
            for (int qq = 0; qq < NQ; qq++)
                tsum[qq] += __shfl_xor_sync(0xffffffffu, tsum[qq], off);
        }
#pragma unroll
        for (int qq = 0; qq < NQ; qq++) inv[qq] = 1.f / tsum[qq];

        // ---- img/lbl softmax in aligned 4-lane groups (24..27, 28..31) ----
        float pg[NQ];
#pragma unroll
        for (int qq = 0; qq < NQ; qq++) {
            float g = sc2[qq];
            g = fmaxf(g, __shfl_xor_sync(0xffffffffu, g, 1));
            g = fmaxf(g, __shfl_xor_sync(0xffffffffu, g, 2));
            const float eg = __expf(sc2[qq] - g);
            float gs = eg;
            gs += __shfl_xor_sync(0xffffffffu, gs, 1);
            gs += __shfl_xor_sync(0xffffffffu, gs, 2);
            pg[qq] = eg / gs;
        }

#pragma unroll
        for (int qq = 0; qq < NQ; qq++) {
            float* P = Pw + qq * 88;
            P[lane]      = e0[qq] * inv[qq];
            P[lane + 32] = e1[qq] * inv[qq];
            if (isTxt2)     P[lane + 64] = e2[qq] * inv[qq];
            if (lane >= 24) P[lane + 53] = pg[qq];
        }
        __syncwarp();

        // ---- output: lane owns dims (lane, lane+32); V shared by NQ queries ----
        float o0[NQ], o1[NQ];
#pragma unroll
        for (int qq = 0; qq < NQ; qq++) { o0[qq] = 0.f; o1[qq] = 0.f; }
#pragma unroll 5
        for (int k = 0; k < LTOT; k++) {
            const float v0 = Vsh[k * KPAD + lane];
            const float v1 = Vsh[k * KPAD + lane + 32];
#pragma unroll
            for (int qq = 0; qq < NQ; qq++) {
                const float p = Pw[qq * 88 + k];
                o0[qq] = fmaf(p, v0, o0[qq]);
                o1[qq] = fmaf(p, v1, o1[qq]);
            }
        }

#pragma unroll
        for (int qq = 0; qq < NQ; qq++) {
            const long long base = ((long long)b * S_ + s + qq) * C_ + h * D_;
            const __nv_bfloat16 h0 = __float2bfloat16(o0[qq]);
            const __nv_bfloat16 h1 = __float2bfloat16(o1[qq]);
            ohi[base + lane]      = h0;
            ohi[base + lane + 32] = h1;
            olo[base + lane]      = __float2bfloat16(o0[qq] - __bfloat162float(h0));
            olo[base + lane + 32] = __float2bfloat16(o1[qq] - __bfloat162float(h1));
        }
        __syncwarp();
    }
}

// ---------------------------------------------------------------------------
// Launch — round-13 structure (monolithic GEMMs; KV branch overlaps Q-GEMM).
// ---------------------------------------------------------------------------
extern "C" void kernel_launch(void* const* d_in, const int* in_sizes, int n_in,
                              void* d_out, int out_size) {
    const float* hidden = (const float*)d_in[0];
    const float* enc    = (const float*)d_in[1];
    const float* Wq     = (const float*)d_in[2];
    const float* Wk     = (const float*)d_in[3];
    const float* Wv     = (const float*)d_in[4];
    const float* Wk_ip  = (const float*)d_in[5];
    const float* Wv_ip  = (const float*)d_in[6];
    const float* Wk_lbl = (const float*)d_in[7];
    const float* Wv_lbl = (const float*)d_in[8];
    const float* Wo     = (const float*)d_in[9];
    const float* bo     = (const float*)d_in[10];
    float* out = (float*)d_out;

    float *qb, *kb, *vb;
    __nv_bfloat16 *ahi, *alo, *wqhi, *wqlo, *wohi;
    cudaGetSymbolAddress((void**)&qb, g_q);
    cudaGetSymbolAddress((void**)&kb, g_k);
    cudaGetSymbolAddress((void**)&vb, g_v);
    cudaGetSymbolAddress((void**)&ahi, g_ahi);
    cudaGetSymbolAddress((void**)&alo, g_alo);
    cudaGetSymbolAddress((void**)&wqhi, g_wqhi);
    cudaGetSymbolAddress((void**)&wqlo, g_wqlo);
    cudaGetSymbolAddress((void**)&wohi, g_wohi);

    // One-time host-side stream/event objects (no device memory involved).
    static cudaStream_t s2 = nullptr;
    static cudaEvent_t evFork = nullptr, evJoin = nullptr;
    if (s2 == nullptr) {
        cudaStreamCreateWithFlags(&s2, cudaStreamNonBlocking);
        cudaEventCreateWithFlags(&evFork, cudaEventDisableTiming);
        cudaEventCreateWithFlags(&evJoin, cudaEventDisableTiming);
    }

    const int SMEM_Q = NSTAGE * (2 * TILEA + 2 * TILEBB);   // 184320
    const int SMEM_O = NSTAGE * (2 * TILEA + 1 * TILEBB);   // 122880
    cudaFuncSetAttribute(gemm_mma<2>,
                         cudaFuncAttributeMaxDynamicSharedMemorySize, SMEM_Q);
    cudaFuncSetAttribute(gemm_mma<1>,
                         cudaFuncAttributeMaxDynamicSharedMemorySize, SMEM_O);
    cudaFuncSetAttribute(attn_kernel,
                         cudaFuncAttributeMaxDynamicSharedMemorySize, ATTN_SMEM);

    // ---- fork: s2 branch starts from the top of the launch ----
    cudaEventRecord(evFork, 0);
    cudaStreamWaitEvent(s2, evFork, 0);

    // ---- s2 branch: memsets + KV projections + Wo conversion ----
    {
        cudaMemsetAsync(kb, 0, (size_t)B_ * LTOT * C_ * sizeof(float), s2);
        cudaMemsetAsync(vb, 0, (size_t)B_ * LTOT * C_ * sizeof(float), s2);
        const long long sA = (long long)LTOT * DC_;
        const long long sC = (long long)LTOT * C_;
        dim3 blk(256);
        dim3 gT(C_ / 64, 3 * KSPLIT, B_);
        dim3 gS(C_ / 64, 1 * KSPLIT, B_);
        sgemm32s<<<gT, blk, 0, s2>>>(enc, Wk, kb, LTXT, sA, sC);
        sgemm32s<<<gT, blk, 0, s2>>>(enc, Wv, vb, LTXT, sA, sC);
        sgemm32s<<<gS, blk, 0, s2>>>(enc + (long long)LTXT * DC_, Wk_ip,
                                     kb + (long long)LTXT * C_, LIMG, sA, sC);
        sgemm32s<<<gS, blk, 0, s2>>>(enc + (long long)LTXT * DC_, Wv_ip,
                                     vb + (long long)LTXT * C_, LIMG, sA, sC);
        sgemm32s<<<gS, blk, 0, s2>>>(enc + (long long)(LTXT + LIMG) * DC_, Wk_lbl,
                                     kb + (long long)(LTXT + LIMG) * C_, LLBL, sA, sC);
        sgemm32s<<<gS, blk, 0, s2>>>(enc + (long long)(LTXT + LIMG) * DC_, Wv_lbl,
                                     vb + (long long)(LTXT + LIMG) * C_, LLBL, sA, sC);
        dim3 gw(C_ / 32, C_ / 32), bw(32, 8);
        conv_w_t<<<gw, bw, 0, s2>>>(Wo, wohi, nullptr);
    }

    // ---- main branch: conversions for Q, then Q projection ----
    {
        const long long n4 = (long long)MTOT * C_ / 4;
        conv_split<<<(unsigned)((n4 + 255) / 256), 256>>>(hidden, ahi, alo, n4);
        dim3 gw(C_ / 32, C_ / 32), bw(32, 8);
        conv_w_t<<<gw, bw>>>(Wq, wqhi, wqlo);
    }
    gemm_mma<2><<<dim3(C_ / 256, MTOT / 128), 256, SMEM_Q>>>(
        ahi, alo, wqhi, wqlo, qb, nullptr, nullptr);

    // ---- join: attention needs K/V; O-GEMM needs wohi ----
    cudaEventRecord(evJoin, s2);
    cudaStreamWaitEvent(0, evJoin, 0);

    // 4. Attention (fp32 Q in, 8 queries/warp) -> bf16 hi/lo activation scratch
    attn_kernel<<<dim3(B_ * H_, 16), 256, ATTN_SMEM>>>(qb, kb, vb, ahi, alo);

    // 5. Output projection: 2-product + bias + residual
    gemm_mma<1><<<dim3(C_ / 256, MTOT / 128), 256, SMEM_O>>>(
        ahi, alo, wohi, nullptr, out, bo, hidden);
}